// round 2
// baseline (speedup 1.0000x reference)
#include <cuda_runtime.h>
#include <math.h>

#define BB 8
#define SS 512
#define DD 256
#define NPAIRS (SS * (SS - 1) / 2)   // 130816
#define NTILES 36                     // 8*9/2 lower-tri 64x64 tiles per batch

// scratch for per-row squared norms (no cudaMalloc allowed)
__device__ float g_norms[BB * SS];

// ---------------------------------------------------------------------------
// Kernel 1: per-row squared L2 norms. One warp per row, float4 loads.
// ---------------------------------------------------------------------------
__global__ __launch_bounds__(256) void norms_kernel(const float* __restrict__ x) {
    int warp = (blockIdx.x * blockDim.x + threadIdx.x) >> 5;
    int lane = threadIdx.x & 31;
    if (warp >= BB * SS) return;
    const float4* x4 = reinterpret_cast<const float4*>(x) + (size_t)warp * (DD / 4);
    float4 a = x4[lane];
    float4 c = x4[lane + 32];
    float s = a.x * a.x + a.y * a.y + a.z * a.z + a.w * a.w
            + c.x * c.x + c.y * c.y + c.z * c.z + c.w * c.w;
#pragma unroll
    for (int o = 16; o; o >>= 1) s += __shfl_xor_sync(0xFFFFFFFFu, s, o);
    if (lane == 0) g_norms[warp] = s;
}

// ---------------------------------------------------------------------------
// Packed f32x2 helpers (sm_100+ PTX; SASS FFMA2 — 2 FMAs per fma-pipe slot)
// ---------------------------------------------------------------------------
__device__ __forceinline__ unsigned long long ffma2(unsigned long long a,
                                                    unsigned long long b,
                                                    unsigned long long c) {
    unsigned long long d;
    asm("fma.rn.f32x2 %0, %1, %2, %3;" : "=l"(d) : "l"(a), "l"(b), "l"(c));
    return d;
}
__device__ __forceinline__ unsigned long long pack2(float v) {
    unsigned long long d;
    asm("mov.b64 %0, {%1, %1};" : "=l"(d) : "f"(v));
    return d;
}
__device__ __forceinline__ float2 unpack2(unsigned long long v) {
    float2 r;
    asm("mov.b64 {%0, %1}, %2;" : "=f"(r.x), "=f"(r.y) : "l"(v));
    return r;
}

// ---------------------------------------------------------------------------
// Kernel 2: 64x64 pair tile per block, 256 threads, 4i x 4j per thread.
// A in smem k-major swizzled (reads give natural f32x2 i-pairs via LDS.128).
// B in smem k-major with each scalar PRE-DUPLICATED into a u64 pair, so the
// inner loop needs zero packing: 3x LDS.128 + 8x FFMA2 per k.
// d^2(i,j) = n_i + n_j - 2*dot(x_i,x_j); out[b][i*(i-1)/2 + j] = sqrt(max(d2,eps))
// ---------------------------------------------------------------------------
__global__ __launch_bounds__(256, 2) void dist_kernel(const float* __restrict__ x,
                                                      float* __restrict__ out) {
    __shared__ __align__(16) float As[64 * 64];                 // 16 KB
    __shared__ __align__(16) unsigned long long Bs[64 * 64];    // 32 KB (duplicated pairs)

    int b = blockIdx.y;
    int t = blockIdx.x;  // triangular tile index: t = ti*(ti+1)/2 + tj
    int ti = 0;
    while ((ti + 1) * (ti + 2) / 2 <= t) ti++;
    int tj = t - ti * (ti + 1) / 2;

    int tid = threadIdx.x;
    int tx = tid & 15;   // 4 i-rows: i0 = 4*tx
    int ty = tid >> 4;   // 4 j-rows: j0 = 4*ty

    const float* xb = x + (size_t)b * SS * DD;
    const float* xa = xb + (size_t)ti * 64 * DD;
    const float* xj = xb + (size_t)tj * 64 * DD;

    // Loader geometry: e = q*256 + tid -> kk4 = e&15 (float4 along k), row = e>>4
    int kk4 = tid & 15;
    int rbase = tid >> 4;  // row = q*16 + rbase

    // Prefetch chunk 0 into registers
    float4 pa[4], pb[4];
#pragma unroll
    for (int q = 0; q < 4; ++q) {
        int row = q * 16 + rbase;
        pa[q] = *reinterpret_cast<const float4*>(xa + row * DD + kk4 * 4);
        pb[q] = *reinterpret_cast<const float4*>(xj + row * DD + kk4 * 4);
    }

    unsigned long long acc[2][4];
#pragma unroll
    for (int p = 0; p < 2; ++p)
#pragma unroll
        for (int v = 0; v < 4; ++v) acc[p][v] = 0ull;

#pragma unroll 1
    for (int ch = 0; ch < 4; ++ch) {
        // ---- store prefetched chunk to smem (swizzle f(k)=k^(k>>2)) ----
#pragma unroll
        for (int q = 0; q < 4; ++q) {
            int row = q * 16 + rbase;
            int cA = row >> 2, subA = row & 3;
            int cB = row >> 1, slot = row & 1;
            float va[4] = {pa[q].x, pa[q].y, pa[q].z, pa[q].w};
            float vb[4] = {pb[q].x, pb[q].y, pb[q].z, pb[q].w};
#pragma unroll
            for (int s = 0; s < 4; ++s) {
                int kk = kk4 * 4 + s;
                int f = kk ^ (kk >> 2);
                As[kk * 64 + ((cA ^ (f & 15)) << 2) + subA] = va[s];
                Bs[kk * 64 + ((cB ^ (f & 31)) << 1) + slot] = pack2(vb[s]);
            }
        }
        __syncthreads();

        // ---- prefetch next chunk (LDG hidden under compute) ----
        if (ch < 3) {
            int k0 = (ch + 1) * 64;
#pragma unroll
            for (int q = 0; q < 4; ++q) {
                int row = q * 16 + rbase;
                pa[q] = *reinterpret_cast<const float4*>(xa + row * DD + k0 + kk4 * 4);
                pb[q] = *reinterpret_cast<const float4*>(xj + row * DD + k0 + kk4 * 4);
            }
        }

        // ---- compute 64 k-steps ----
        const ulonglong2* Asu = reinterpret_cast<const ulonglong2*>(As);
        const ulonglong2* Bsu = reinterpret_cast<const ulonglong2*>(Bs);
#pragma unroll 16
        for (int k = 0; k < 64; ++k) {
            int f = k ^ (k >> 2);
            ulonglong2 av = Asu[k * 16 + (tx ^ (f & 15))];          // (i0,i1),(i2,i3)
            ulonglong2 b0 = Bsu[k * 32 + ((2 * ty) ^ (f & 31))];    // (j0,j0),(j1,j1)
            ulonglong2 b1 = Bsu[k * 32 + ((2 * ty + 1) ^ (f & 31))];// (j2,j2),(j3,j3)
            acc[0][0] = ffma2(av.x, b0.x, acc[0][0]);
            acc[0][1] = ffma2(av.x, b0.y, acc[0][1]);
            acc[0][2] = ffma2(av.x, b1.x, acc[0][2]);
            acc[0][3] = ffma2(av.x, b1.y, acc[0][3]);
            acc[1][0] = ffma2(av.y, b0.x, acc[1][0]);
            acc[1][1] = ffma2(av.y, b0.y, acc[1][1]);
            acc[1][2] = ffma2(av.y, b1.x, acc[1][2]);
            acc[1][3] = ffma2(av.y, b1.y, acc[1][3]);
        }
        __syncthreads();
    }

    // ---- epilogue: combine with norms, write strict lower triangle ----
    int i0 = ti * 64 + 4 * tx;
    int j0 = tj * 64 + 4 * ty;
    float ni[4], nj[4];
#pragma unroll
    for (int u = 0; u < 4; ++u) ni[u] = g_norms[b * SS + i0 + u];
#pragma unroll
    for (int v = 0; v < 4; ++v) nj[v] = g_norms[b * SS + j0 + v];

    float* ob = out + (size_t)b * NPAIRS;
#pragma unroll
    for (int p = 0; p < 2; ++p) {
#pragma unroll
        for (int v = 0; v < 4; ++v) {
            float2 dv = unpack2(acc[p][v]);
            int j = j0 + v;
            int ia = i0 + 2 * p;
            int ib = ia + 1;
            if (j < ia) {
                float d2 = ni[2 * p] + nj[v] - 2.0f * dv.x;
                ob[ia * (ia - 1) / 2 + j] = sqrtf(fmaxf(d2, 1e-7f));
            }
            if (j < ib) {
                float d2 = ni[2 * p + 1] + nj[v] - 2.0f * dv.y;
                ob[ib * (ib - 1) / 2 + j] = sqrtf(fmaxf(d2, 1e-7f));
            }
        }
    }
}

// ---------------------------------------------------------------------------
extern "C" void kernel_launch(void* const* d_in, const int* in_sizes, int n_in,
                              void* d_out, int out_size) {
    const float* x = (const float*)d_in[0];
    float* out = (float*)d_out;

    norms_kernel<<<512, 256>>>(x);

    dim3 grid(NTILES, BB);
    dist_kernel<<<grid, 256>>>(x, out);
}

// round 4
// speedup vs baseline: 1.4444x; 1.4444x over previous
#include <cuda_runtime.h>
#include <cuda_bf16.h>
#include <cstdint>
#include <math.h>

#define BB 8
#define SS 512
#define DD 256
#define NPAIRS (SS * (SS - 1) / 2)   // 130816
#define TILE 128
#define NT (SS / TILE)               // 4
#define NTRI (NT * (NT + 1) / 2)     // 10 lower-tri 128x128 tiles per batch
#define KTOT 768                     // [hi|hi|lo] x [hi|lo|hi]
#define KC 64                        // K per smem chunk (128B rows)
#define NCH (KTOT / KC)              // 12

// ---- device globals (no cudaMalloc allowed) ----
__device__ float g_norms[BB * SS];
__device__ __align__(16) __nv_bfloat16 g_a[BB * SS * KTOT];  // [hi|hi|lo]
__device__ __align__(16) __nv_bfloat16 g_b[BB * SS * KTOT];  // [hi|lo|hi]

// ---------------------------------------------------------------------------
__device__ __forceinline__ uint32_t smem_u32(const void* p) {
    uint32_t a;
    asm("{ .reg .u64 t; cvta.to.shared.u64 t, %1; cvt.u32.u64 %0, t; }" : "=r"(a) : "l"(p));
    return a;
}
__device__ __forceinline__ void cp_async16(uint32_t dst, const void* src) {
    asm volatile("cp.async.cg.shared.global [%0], [%1], 16;" :: "r"(dst), "l"(src) : "memory");
}
__device__ __forceinline__ void cp_commit() { asm volatile("cp.async.commit_group;" ::: "memory"); }
__device__ __forceinline__ void ldm_x4(uint32_t& r0, uint32_t& r1, uint32_t& r2, uint32_t& r3,
                                       uint32_t addr) {
    asm volatile("ldmatrix.sync.aligned.m8n8.x4.shared.b16 {%0,%1,%2,%3}, [%4];"
                 : "=r"(r0), "=r"(r1), "=r"(r2), "=r"(r3) : "r"(addr));
}
__device__ __forceinline__ void mma_bf16(float* d, const uint32_t* a, const uint32_t* bfr) {
    asm volatile(
        "mma.sync.aligned.m16n8k16.row.col.f32.bf16.bf16.f32 "
        "{%0,%1,%2,%3}, {%4,%5,%6,%7}, {%8,%9}, {%0,%1,%2,%3};"
        : "+f"(d[0]), "+f"(d[1]), "+f"(d[2]), "+f"(d[3])
        : "r"(a[0]), "r"(a[1]), "r"(a[2]), "r"(a[3]), "r"(bfr[0]), "r"(bfr[1]));
}

// ---------------------------------------------------------------------------
// Kernel 1: per-row norms (fp32) + hi/lo bf16 split into concat layouts.
// One warp per row; lane handles elems [4*lane,4*lane+4) and +128.
// ---------------------------------------------------------------------------
__global__ __launch_bounds__(256) void prep_kernel(const float* __restrict__ x) {
    int row = blockIdx.x * 8 + (threadIdx.x >> 5);
    int lane = threadIdx.x & 31;
    if (row >= BB * SS) return;
    const float4* x4 = reinterpret_cast<const float4*>(x) + (size_t)row * (DD / 4);
    float4 a = x4[lane];
    float4 c = x4[lane + 32];
    float s = a.x * a.x + a.y * a.y + a.z * a.z + a.w * a.w
            + c.x * c.x + c.y * c.y + c.z * c.z + c.w * c.w;
#pragma unroll
    for (int o = 16; o; o >>= 1) s += __shfl_xor_sync(0xFFFFFFFFu, s, o);
    if (lane == 0) g_norms[row] = s;

    size_t ab = (size_t)row * KTOT;
#pragma unroll
    for (int g = 0; g < 2; ++g) {
        float4 v = g ? c : a;
        int k = lane * 4 + g * 128;
        __nv_bfloat162 h0 = __floats2bfloat162_rn(v.x, v.y);
        __nv_bfloat162 h1 = __floats2bfloat162_rn(v.z, v.w);
        __nv_bfloat162 l0 = __floats2bfloat162_rn(v.x - __low2float(h0), v.y - __high2float(h0));
        __nv_bfloat162 l1 = __floats2bfloat162_rn(v.z - __low2float(h1), v.w - __high2float(h1));
        uint2 hv = make_uint2(*(uint32_t*)&h0, *(uint32_t*)&h1);
        uint2 lv = make_uint2(*(uint32_t*)&l0, *(uint32_t*)&l1);
        // A' = [hi|hi|lo]
        *reinterpret_cast<uint2*>(g_a + ab + k)       = hv;
        *reinterpret_cast<uint2*>(g_a + ab + 256 + k) = hv;
        *reinterpret_cast<uint2*>(g_a + ab + 512 + k) = lv;
        // B' = [hi|lo|hi]
        *reinterpret_cast<uint2*>(g_b + ab + k)       = hv;
        *reinterpret_cast<uint2*>(g_b + ab + 256 + k) = lv;
        *reinterpret_cast<uint2*>(g_b + ab + 512 + k) = hv;
    }
}

// ---------------------------------------------------------------------------
// Kernel 2: 128x128 Gram tile per CTA, 8 warps (2m x 4n), warp tile 64x32.
// K=768 streamed in 12 chunks of 64; cp.async double buffer; mma.sync bf16.
// smem: si[128] f32, sj[128] f32, then 2 buffers x (A 16KB + B 16KB).
// ---------------------------------------------------------------------------
#define SM_NORM 1024
#define BUF_BYTES 32768
#define SMEM_TOTAL (SM_NORM + 2 * BUF_BYTES)

__global__ __launch_bounds__(256, 1) void dist_kernel(float* __restrict__ out) {
    extern __shared__ char smem[];
    uint32_t sbase = smem_u32(smem);
    int tid = threadIdx.x;
    int lane = tid & 31;
    int wid = tid >> 5;
    int wm = wid >> 2;   // 0..1 -> m offset 64*wm
    int wn = wid & 3;    // 0..3 -> n offset 32*wn

    int b = blockIdx.y;
    int t = blockIdx.x;
    int ti = 0;
    while ((ti + 1) * (ti + 2) / 2 <= t) ti++;
    int tj = t - ti * (ti + 1) / 2;

    // stage norms
    float* si = reinterpret_cast<float*>(smem);          // rows (i)
    float* sjn = reinterpret_cast<float*>(smem + 512);   // cols (j)
    if (tid < 128) si[tid] = g_norms[b * SS + ti * TILE + tid];
    else sjn[tid - 128] = g_norms[b * SS + tj * TILE + (tid - 128)];

    // loader geometry: rr = tid>>3 (+0/32/64/96), cc = tid&7 (16B chunk)
    int rr = tid >> 3, cc = tid & 7;
    const __nv_bfloat16* pAg = g_a + ((size_t)(b * SS + ti * TILE) + rr) * KTOT + cc * 8;
    const __nv_bfloat16* pBg = g_b + ((size_t)(b * SS + tj * TILE) + rr) * KTOT + cc * 8;
    uint32_t swL = (cc * 16) ^ ((rr & 7) << 4);
    uint32_t dA = sbase + SM_NORM + rr * 128 + swL;
    uint32_t dB = dA + 16384;

    auto issue_chunk = [&](int ch, int bufi) {
        uint32_t bo = bufi * BUF_BYTES;
        const __nv_bfloat16* sa = pAg + ch * KC;
        const __nv_bfloat16* sb = pBg + ch * KC;
#pragma unroll
        for (int q = 0; q < 4; ++q) {
            cp_async16(dA + bo + q * 4096, sa + (size_t)q * 32 * KTOT);
            cp_async16(dB + bo + q * 4096, sb + (size_t)q * 32 * KTOT);
        }
        cp_commit();
    };

    // per-lane ldmatrix addressing
    int rA = lane & 15;                      // A row within 16-block
    int kselA = (lane >> 4) & 1;             // +8 k -> +1 chunk
    int rB = (lane & 7) | ((lane >> 1) & 8); // B row within 16-block
    int kselB = (lane >> 3) & 1;
    uint32_t aRow = sbase + SM_NORM + (wm * 64 + rA) * 128;
    uint32_t bRow = sbase + SM_NORM + 16384 + (wn * 32 + rB) * 128;
    uint32_t swA[4], swB[4];
#pragma unroll
    for (int ks = 0; ks < 4; ++ks) {
        swA[ks] = ((ks * 2 + kselA) * 16) ^ ((rA & 7) << 4);
        swB[ks] = ((ks * 2 + kselB) * 16) ^ ((rB & 7) << 4);
    }

    float acc[4][4][4];
#pragma unroll
    for (int mt = 0; mt < 4; ++mt)
#pragma unroll
        for (int nt = 0; nt < 4; ++nt)
#pragma unroll
            for (int e = 0; e < 4; ++e) acc[mt][nt][e] = 0.0f;

    issue_chunk(0, 0);

#pragma unroll 1
    for (int ch = 0; ch < NCH; ++ch) {
        int bufi = ch & 1;
        if (ch < NCH - 1) {
            issue_chunk(ch + 1, bufi ^ 1);
            asm volatile("cp.async.wait_group 1;" ::: "memory");
        } else {
            asm volatile("cp.async.wait_group 0;" ::: "memory");
        }
        __syncthreads();

        uint32_t bo = bufi * BUF_BYTES;
#pragma unroll
        for (int ks = 0; ks < 4; ++ks) {
            uint32_t afr[4][4], bfr[2][4];
#pragma unroll
            for (int mt = 0; mt < 4; ++mt)
                ldm_x4(afr[mt][0], afr[mt][1], afr[mt][2], afr[mt][3],
                       aRow + bo + mt * 2048 + swA[ks]);
#pragma unroll
            for (int nh = 0; nh < 2; ++nh)
                ldm_x4(bfr[nh][0], bfr[nh][1], bfr[nh][2], bfr[nh][3],
                       bRow + bo + nh * 2048 + swB[ks]);
#pragma unroll
            for (int mt = 0; mt < 4; ++mt) {
#pragma unroll
                for (int nt = 0; nt < 4; ++nt) {
                    uint32_t bb2[2] = { bfr[nt >> 1][(nt & 1) * 2],
                                        bfr[nt >> 1][(nt & 1) * 2 + 1] };
                    // matrix order in bfr: {n0-7 k0-7, n0-7 k8-15, n8-15 k0-7, n8-15 k8-15}
                    mma_bf16(acc[mt][nt], afr[mt], bb2);
                }
            }
        }
        __syncthreads();
    }

    // ---- epilogue ----
    int lr = lane >> 2;            // 0..7
    int lc = 2 * (lane & 3);       // 0,2,4,6
    float* ob = out + (size_t)b * NPAIRS;
#pragma unroll
    for (int mt = 0; mt < 4; ++mt) {
        int r0 = wm * 64 + mt * 16 + lr;
        int i0 = ti * TILE + r0;
        int i1 = i0 + 8;
        float n0 = si[r0], n1 = si[r0 + 8];
        long long base0 = (long long)i0 * (i0 - 1) / 2;
        long long base1 = (long long)i1 * (i1 - 1) / 2;
#pragma unroll
        for (int nt = 0; nt < 4; ++nt) {
            int col = wn * 32 + nt * 8 + lc;
            int j = tj * TILE + col;
            float njc0 = sjn[col], njc1 = sjn[col + 1];
            float* c = acc[mt][nt];
            if (j < i0)     ob[base0 + j]     = sqrtf(fmaxf(n0 + njc0 - 2.0f * c[0], 1e-7f));
            if (j + 1 < i0) ob[base0 + j + 1] = sqrtf(fmaxf(n0 + njc1 - 2.0f * c[1], 1e-7f));
            if (j < i1)     ob[base1 + j]     = sqrtf(fmaxf(n1 + njc0 - 2.0f * c[2], 1e-7f));
            if (j + 1 < i1) ob[base1 + j + 1] = sqrtf(fmaxf(n1 + njc1 - 2.0f * c[3], 1e-7f));
        }
    }
}

// ---------------------------------------------------------------------------
extern "C" void kernel_launch(void* const* d_in, const int* in_sizes, int n_in,
                              void* d_out, int out_size) {
    const float* x = (const float*)d_in[0];
    float* out = (float*)d_out;

    static bool attr_done = false;
    if (!attr_done) {
        cudaFuncSetAttribute(dist_kernel, cudaFuncAttributeMaxDynamicSharedMemorySize,
                             SMEM_TOTAL);
        attr_done = true;
    }

    prep_kernel<<<512, 256>>>(x);

    dim3 grid(NTRI, BB);
    dist_kernel<<<grid, 256, SMEM_TOTAL>>>(out);
}

// round 5
// speedup vs baseline: 3.0321x; 2.0991x over previous
#include <cuda_runtime.h>
#include <cuda_fp16.h>
#include <cstdint>
#include <math.h>

#define BB 8
#define SS 512
#define DD 256
#define NPAIRS (SS * (SS - 1) / 2)   // 130816
#define TILE 64
#define NT (SS / TILE)               // 8
#define NTRI (NT * (NT + 1) / 2)     // 36 lower-tri 64x64 tiles per batch
#define KC 128                       // K per smem chunk (256B rows)
#define NCH (DD / KC)                // 2

// ---- device globals (no cudaMalloc allowed) ----
__device__ float g_norms[BB * SS];
__device__ __align__(16) __half g_h[BB * SS * DD];   // fp16(x), 2MB

// ---------------------------------------------------------------------------
__device__ __forceinline__ uint32_t smem_u32(const void* p) {
    uint32_t a;
    asm("{ .reg .u64 t; cvta.to.shared.u64 t, %1; cvt.u32.u64 %0, t; }" : "=r"(a) : "l"(p));
    return a;
}
__device__ __forceinline__ void cp_async16(uint32_t dst, const void* src) {
    asm volatile("cp.async.cg.shared.global [%0], [%1], 16;" :: "r"(dst), "l"(src) : "memory");
}
__device__ __forceinline__ void cp_commit() { asm volatile("cp.async.commit_group;" ::: "memory"); }
__device__ __forceinline__ void ldm_x4(uint32_t& r0, uint32_t& r1, uint32_t& r2, uint32_t& r3,
                                       uint32_t addr) {
    asm volatile("ldmatrix.sync.aligned.m8n8.x4.shared.b16 {%0,%1,%2,%3}, [%4];"
                 : "=r"(r0), "=r"(r1), "=r"(r2), "=r"(r3) : "r"(addr));
}
__device__ __forceinline__ void mma_f16(float* d, const uint32_t* a, const uint32_t* bfr) {
    asm volatile(
        "mma.sync.aligned.m16n8k16.row.col.f32.f16.f16.f32 "
        "{%0,%1,%2,%3}, {%4,%5,%6,%7}, {%8,%9}, {%0,%1,%2,%3};"
        : "+f"(d[0]), "+f"(d[1]), "+f"(d[2]), "+f"(d[3])
        : "r"(a[0]), "r"(a[1]), "r"(a[2]), "r"(a[3]), "r"(bfr[0]), "r"(bfr[1]));
}

// ---------------------------------------------------------------------------
// Kernel 1: per-row norms (exact fp32) + fp16 conversion. One warp per row.
// ---------------------------------------------------------------------------
__global__ __launch_bounds__(256) void prep_kernel(const float* __restrict__ x) {
    int row = blockIdx.x * 8 + (threadIdx.x >> 5);
    int lane = threadIdx.x & 31;
    if (row >= BB * SS) return;
    const float4* x4 = reinterpret_cast<const float4*>(x) + (size_t)row * (DD / 4);
    float4 a = x4[lane];
    float4 c = x4[lane + 32];
    float s = a.x * a.x + a.y * a.y + a.z * a.z + a.w * a.w
            + c.x * c.x + c.y * c.y + c.z * c.z + c.w * c.w;
#pragma unroll
    for (int o = 16; o; o >>= 1) s += __shfl_xor_sync(0xFFFFFFFFu, s, o);
    if (lane == 0) g_norms[row] = s;

    size_t base = (size_t)row * DD;
#pragma unroll
    for (int g = 0; g < 2; ++g) {
        float4 v = g ? c : a;
        __half2 h0 = __floats2half2_rn(v.x, v.y);
        __half2 h1 = __floats2half2_rn(v.z, v.w);
        uint2 hv = make_uint2(*(uint32_t*)&h0, *(uint32_t*)&h1);
        *reinterpret_cast<uint2*>(g_h + base + g * 128 + lane * 4) = hv;
    }
}

// ---------------------------------------------------------------------------
// Kernel 2: 64x64 Gram tile per CTA, 4 warps (2x2, warp tile 32x32).
// K=256 in 2 chunks of 128 (256B smem rows, XOR-16B swizzle), cp.async
// double-buffered; mma.sync fp16->fp32; register-pipelined ldmatrix.
// smem: si[64], sj[64] f32 (512B), then 2 bufs x (A 16KB + B 16KB).
// ---------------------------------------------------------------------------
#define SM_NORM 512
#define MAT_BYTES 16384              // 64 rows x 256B
#define BUF_BYTES (2 * MAT_BYTES)
#define SMEM_TOTAL (SM_NORM + 2 * BUF_BYTES)

__global__ __launch_bounds__(128, 2) void dist_kernel(float* __restrict__ out) {
    extern __shared__ char smem[];
    uint32_t sbase = smem_u32(smem);
    int tid = threadIdx.x;
    int lane = tid & 31;
    int wid = tid >> 5;
    int wtm = wid >> 1;  // 0..1 -> m offset 32*wtm
    int wtn = wid & 1;   // 0..1 -> n offset 32*wtn

    int b = blockIdx.y;
    int t = blockIdx.x;
    int ti = 0;
    while ((ti + 1) * (ti + 2) / 2 <= t) ti++;
    int tj = t - ti * (ti + 1) / 2;

    // stage norms
    float* si = reinterpret_cast<float*>(smem);          // rows (i)
    float* sjn = reinterpret_cast<float*>(smem + 256);   // cols (j)
    if (tid < 64) si[tid] = g_norms[b * SS + ti * TILE + tid];
    else if (tid < 128) sjn[tid - 64] = g_norms[b * SS + tj * TILE + (tid - 64)];

    // loader geometry: kk = tid&15 (16B chunk of a 256B row-chunk), row8 = tid>>4
    int kk = tid & 15, row8 = tid >> 4;
    const __half* pAg = g_h + ((size_t)(b * SS + ti * TILE) + row8) * DD + kk * 8;
    const __half* pBg = g_h + ((size_t)(b * SS + tj * TILE) + row8) * DD + kk * 8;
    uint32_t dA = sbase + SM_NORM + row8 * 256 + ((kk ^ (row8 & 7)) * 16);
    uint32_t dB = dA + MAT_BYTES;

    auto issue_chunk = [&](int ch, int bufi) {
        uint32_t bo = bufi * BUF_BYTES;
        const __half* sa = pAg + ch * KC;
        const __half* sb = pBg + ch * KC;
#pragma unroll
        for (int q = 0; q < 8; ++q) {   // rows row8 + 8q
            cp_async16(dA + bo + q * 2048, sa + (size_t)q * 8 * DD);
            cp_async16(dB + bo + q * 2048, sb + (size_t)q * 8 * DD);
        }
        cp_commit();
    };

    // per-lane ldmatrix addressing (row stride 256B, 16 slots/row)
    int rA = lane & 15;
    int kselA = (lane >> 4) & 1;
    int rB = (lane & 7) | ((lane >> 1) & 8);
    int kselB = (lane >> 3) & 1;
    uint32_t aRow = sbase + SM_NORM + (wtm * 32 + rA) * 256;
    uint32_t bRow = sbase + SM_NORM + MAT_BYTES + (wtn * 32 + rB) * 256;

    float acc[2][4][4];
#pragma unroll
    for (int mt = 0; mt < 2; ++mt)
#pragma unroll
        for (int nt = 0; nt < 4; ++nt)
#pragma unroll
            for (int e = 0; e < 4; ++e) acc[mt][nt][e] = 0.0f;

    issue_chunk(0, 0);
    issue_chunk(1, 1);

    uint32_t afr[2][2][4], bfr[2][2][4];  // [pipe][mt|nh][frag]
    auto load_frags = [&](int p, int bufi, int ks) {
        uint32_t bo = bufi * BUF_BYTES;
        uint32_t swA = ((ks * 2 + kselA) ^ (rA & 7)) * 16;
        uint32_t swB = ((ks * 2 + kselB) ^ (rB & 7)) * 16;
#pragma unroll
        for (int mt = 0; mt < 2; ++mt)
            ldm_x4(afr[p][mt][0], afr[p][mt][1], afr[p][mt][2], afr[p][mt][3],
                   aRow + bo + mt * 4096 + swA);
#pragma unroll
        for (int nh = 0; nh < 2; ++nh)
            ldm_x4(bfr[p][nh][0], bfr[p][nh][1], bfr[p][nh][2], bfr[p][nh][3],
                   bRow + bo + nh * 4096 + swB);
    };
    auto do_mma = [&](int p) {
#pragma unroll
        for (int mt = 0; mt < 2; ++mt)
#pragma unroll
            for (int nt = 0; nt < 4; ++nt) {
                uint32_t bb2[2] = { bfr[p][nt >> 1][(nt & 1) * 2],
                                    bfr[p][nt >> 1][(nt & 1) * 2 + 1] };
                mma_f16(acc[mt][nt], afr[p][mt], bb2);
            }
    };

    // chunk 0 ready
    asm volatile("cp.async.wait_group 1;" ::: "memory");
    __syncthreads();

    load_frags(0, 0, 0);
#pragma unroll
    for (int ks = 0; ks < 8; ++ks) {
        if (ks < 7) load_frags((ks + 1) & 1, 0, ks + 1);
        do_mma(ks & 1);
    }

    // chunk 1 ready
    asm volatile("cp.async.wait_group 0;" ::: "memory");
    __syncthreads();

    load_frags(0, 1, 0);
#pragma unroll
    for (int ks = 0; ks < 8; ++ks) {
        if (ks < 7) load_frags((ks + 1) & 1, 1, ks + 1);
        do_mma(ks & 1);
    }

    // ---- epilogue ----
    int lr = lane >> 2;            // 0..7
    int lc = 2 * (lane & 3);       // 0,2,4,6
    float* ob = out + (size_t)b * NPAIRS;
#pragma unroll
    for (int mt = 0; mt < 2; ++mt) {
        int r0 = wtm * 32 + mt * 16 + lr;
        int i0 = ti * TILE + r0;
        int i1 = i0 + 8;
        float n0 = si[r0], n1 = si[r0 + 8];
        int base0 = i0 * (i0 - 1) / 2;
        int base1 = i1 * (i1 - 1) / 2;
#pragma unroll
        for (int nt = 0; nt < 4; ++nt) {
            int col = wtn * 32 + nt * 8 + lc;
            int j = tj * TILE + col;
            float njc0 = sjn[col], njc1 = sjn[col + 1];
            float* c = acc[mt][nt];
            if (j < i0)     ob[base0 + j]     = sqrtf(fmaxf(n0 + njc0 - 2.0f * c[0], 1e-7f));
            if (j + 1 < i0) ob[base0 + j + 1] = sqrtf(fmaxf(n0 + njc1 - 2.0f * c[1], 1e-7f));
            if (j < i1)     ob[base1 + j]     = sqrtf(fmaxf(n1 + njc0 - 2.0f * c[2], 1e-7f));
            if (j + 1 < i1) ob[base1 + j + 1] = sqrtf(fmaxf(n1 + njc1 - 2.0f * c[3], 1e-7f));
        }
    }
}

// ---------------------------------------------------------------------------
extern "C" void kernel_launch(void* const* d_in, const int* in_sizes, int n_in,
                              void* d_out, int out_size) {
    const float* x = (const float*)d_in[0];
    float* out = (float*)d_out;

    static bool attr_done = false;
    if (!attr_done) {
        cudaFuncSetAttribute(dist_kernel, cudaFuncAttributeMaxDynamicSharedMemorySize,
                             SMEM_TOTAL);
        attr_done = true;
    }

    prep_kernel<<<512, 256>>>(x);

    dim3 grid(NTRI, BB);
    dist_kernel<<<grid, 128, SMEM_TOTAL>>>(out);
}